// round 1
// baseline (speedup 1.0000x reference)
#include <cuda_runtime.h>
#include <math.h>

// Problem constants
#define B_   8
#define L_   8192
#define D_   512
#define H_   8
#define DH_  64
#define D3_  1536
#define M_   (B_ * L_)      // 65536 rows
#define EPS_ 1e-6f
#define NSC  16             // s-chunks for kv partial sums
#define SCHUNK (L_ / NSC)   // 512

// ---------------------------------------------------------------------------
// Scratch (static __device__ globals; no allocations anywhere)
// ---------------------------------------------------------------------------
__device__ float g_X  [M_ * D3_];        // concat(q,k,v)            402 MB
__device__ float g_QKV[M_ * D3_];        // qkv projection output    402 MB
__device__ float g_ATT[M_ * D_];         // attention output         134 MB
__device__ float g_KVP[NSC * B_ * H_ * DH_ * DH_]; // kv partials    16 MB
__device__ float g_KSP[NSC * B_ * H_ * DH_];       // ksum partials
__device__ float g_KV [B_ * H_ * DH_ * DH_];
__device__ float g_KS [B_ * H_ * DH_];

// ---------------------------------------------------------------------------
// 1) Concat q,k,v -> X [M, 1536]  (float4 throughout)
// ---------------------------------------------------------------------------
__global__ void concat_k(const float4* __restrict__ q,
                         const float4* __restrict__ k,
                         const float4* __restrict__ v) {
    int i = blockIdx.x * 256 + threadIdx.x;     // exactly M_*128 threads
    int n = i >> 7;
    int c = i & 127;
    float4* X = reinterpret_cast<float4*>(g_X);
    size_t base = (size_t)n * 384;
    X[base + c]       = q[i];
    X[base + 128 + c] = k[i];
    X[base + 256 + c] = v[i];
}

// ---------------------------------------------------------------------------
// 2) SGEMM (NT): C[M,N] = A[M,K] @ B[N,K]^T (+ optional bias[N])
//    128x128 block tile, BK=16, 256 threads, 8x8 per-thread microtile.
//    Requires M%128==0, N%128==0, K%16==0 (true for all uses here).
// ---------------------------------------------------------------------------
__global__ __launch_bounds__(256)
void sgemm_nt(const float* __restrict__ A, const float* __restrict__ Bm,
              const float* __restrict__ bias, float* __restrict__ C,
              int N, int K) {
    __shared__ float As[16][128];
    __shared__ float Bs[16][128];

    const int tid = threadIdx.x;
    const int tx  = tid & 15;
    const int ty  = tid >> 4;

    const float* Ab = A  + (size_t)blockIdx.y * 128 * K;
    const float* Bb = Bm + (size_t)blockIdx.x * 128 * K;

    float acc[8][8] = {};

    for (int k0 = 0; k0 < K; k0 += 16) {
        #pragma unroll
        for (int i = 0; i < 2; i++) {
            int idx = tid + i * 256;
            int row = idx >> 2;
            int c4  = (idx & 3) * 4;
            float4 va = *reinterpret_cast<const float4*>(Ab + (size_t)row * K + k0 + c4);
            As[c4 + 0][row] = va.x; As[c4 + 1][row] = va.y;
            As[c4 + 2][row] = va.z; As[c4 + 3][row] = va.w;
            float4 vb = *reinterpret_cast<const float4*>(Bb + (size_t)row * K + k0 + c4);
            Bs[c4 + 0][row] = vb.x; Bs[c4 + 1][row] = vb.y;
            Bs[c4 + 2][row] = vb.z; Bs[c4 + 3][row] = vb.w;
        }
        __syncthreads();

        #pragma unroll
        for (int kk = 0; kk < 16; kk++) {
            float ar[8], br[8];
            *reinterpret_cast<float4*>(&ar[0]) = *reinterpret_cast<const float4*>(&As[kk][ty * 8]);
            *reinterpret_cast<float4*>(&ar[4]) = *reinterpret_cast<const float4*>(&As[kk][ty * 8 + 4]);
            *reinterpret_cast<float4*>(&br[0]) = *reinterpret_cast<const float4*>(&Bs[kk][tx * 8]);
            *reinterpret_cast<float4*>(&br[4]) = *reinterpret_cast<const float4*>(&Bs[kk][tx * 8 + 4]);
            #pragma unroll
            for (int i = 0; i < 8; i++)
                #pragma unroll
                for (int j = 0; j < 8; j++)
                    acc[i][j] = fmaf(ar[i], br[j], acc[i][j]);
        }
        __syncthreads();
    }

    const int rowb = blockIdx.y * 128 + ty * 8;
    const int colb = blockIdx.x * 128 + tx * 8;
    float bv[8];
    #pragma unroll
    for (int j = 0; j < 8; j++) bv[j] = bias ? bias[colb + j] : 0.0f;

    #pragma unroll
    for (int i = 0; i < 8; i++) {
        float4 o0, o1;
        o0.x = acc[i][0] + bv[0]; o0.y = acc[i][1] + bv[1];
        o0.z = acc[i][2] + bv[2]; o0.w = acc[i][3] + bv[3];
        o1.x = acc[i][4] + bv[4]; o1.y = acc[i][5] + bv[5];
        o1.z = acc[i][6] + bv[6]; o1.w = acc[i][7] + bv[7];
        float* cp = C + (size_t)(rowb + i) * N + colb;
        *reinterpret_cast<float4*>(cp)     = o0;
        *reinterpret_cast<float4*>(cp + 4) = o1;
    }
}

// ---------------------------------------------------------------------------
// 3) elu+1 feature map on q & k parts of QKV (cols [0,1024) of each row)
// ---------------------------------------------------------------------------
__device__ __forceinline__ float elu1(float x) {
    return x > 0.0f ? x + 1.0f : expf(x);
}

__global__ void elu_k() {
    int i = blockIdx.x * 256 + threadIdx.x;     // exactly M_*256 threads
    int n = i >> 8;
    int c = i & 255;                            // 256 float4 = cols [0,1024)
    float4* Q = reinterpret_cast<float4*>(g_QKV);
    size_t idx = (size_t)n * 384 + c;
    float4 v = Q[idx];
    v.x = elu1(v.x); v.y = elu1(v.y); v.z = elu1(v.z); v.w = elu1(v.w);
    Q[idx] = v;
}

// ---------------------------------------------------------------------------
// 4) kv state partials: for each (b,h,sc):
//    KVP[sc,bh,m,d] = sum_{s in chunk} k[s,d] * v[s,m]
//    KSP[sc,bh,d]   = sum_{s in chunk} k[s,d]
//    Deterministic (no atomics) -> graph replays are bit-stable.
// ---------------------------------------------------------------------------
__global__ __launch_bounds__(256)
void kv_kernel() {
    __shared__ float ks[16][64];
    __shared__ float vs[16][64];

    const int bh = blockIdx.x;   // 0..63
    const int sc = blockIdx.y;   // 0..15
    const int b  = bh >> 3;
    const int h  = bh & 7;
    const int tid = threadIdx.x;
    const int tx  = tid & 15;
    const int ty  = tid >> 4;
    const int lrow = tid >> 4;           // 0..15
    const int lc   = (tid & 15) * 4;     // 0..60

    float acc[4][4] = {};
    float ksa[4] = {0.f, 0.f, 0.f, 0.f};

    const size_t rowbase = ((size_t)b * L_ + (size_t)sc * SCHUNK) * D3_;
    const float* kp = g_QKV + rowbase + D_     + h * DH_;
    const float* vp = g_QKV + rowbase + 2 * D_ + h * DH_;

    for (int it = 0; it < SCHUNK; it += 16) {
        size_t off = (size_t)(it + lrow) * D3_ + lc;
        *reinterpret_cast<float4*>(&ks[lrow][lc]) = *reinterpret_cast<const float4*>(kp + off);
        *reinterpret_cast<float4*>(&vs[lrow][lc]) = *reinterpret_cast<const float4*>(vp + off);
        __syncthreads();

        #pragma unroll
        for (int ss = 0; ss < 16; ss++) {
            float kr[4], vr[4];
            *reinterpret_cast<float4*>(kr) = *reinterpret_cast<const float4*>(&ks[ss][tx * 4]);
            *reinterpret_cast<float4*>(vr) = *reinterpret_cast<const float4*>(&vs[ss][ty * 4]);
            #pragma unroll
            for (int i = 0; i < 4; i++)
                #pragma unroll
                for (int j = 0; j < 4; j++)
                    acc[i][j] = fmaf(vr[i], kr[j], acc[i][j]);
            if (ty == 0) {
                #pragma unroll
                for (int j = 0; j < 4; j++) ksa[j] += kr[j];
            }
        }
        __syncthreads();
    }

    float* kvp = g_KVP + ((size_t)sc * 64 + bh) * 4096;
    #pragma unroll
    for (int i = 0; i < 4; i++)
        #pragma unroll
        for (int j = 0; j < 4; j++)
            kvp[(ty * 4 + i) * 64 + tx * 4 + j] = acc[i][j];

    if (ty == 0) {
        float* ksp = g_KSP + ((size_t)sc * 64 + bh) * 64 + tx * 4;
        #pragma unroll
        for (int j = 0; j < 4; j++) ksp[j] = ksa[j];
    }
}

// ---------------------------------------------------------------------------
// 5) Reduce partials -> KV, KS
// ---------------------------------------------------------------------------
__global__ void kv_reduce() {
    int i = blockIdx.x * 256 + threadIdx.x;     // 266240 threads (exact)
    if (i < 262144) {
        float s = 0.f;
        #pragma unroll
        for (int sc = 0; sc < NSC; sc++) s += g_KVP[sc * 262144 + i];
        g_KV[i] = s;
    } else {
        int j = i - 262144;                     // 0..4095
        float s = 0.f;
        #pragma unroll
        for (int sc = 0; sc < NSC; sc++) s += g_KSP[sc * 4096 + j];
        g_KS[j] = s;
    }
}

// ---------------------------------------------------------------------------
// 6) Attention apply: out[l,h,m] = z * sum_d q[l,h,d] * KV[h][m,d]
//    z = 1 / (sum_d q[d] * KS[d] + eps)
// ---------------------------------------------------------------------------
__global__ __launch_bounds__(256)
void attn_k() {
    __shared__ float kvs[64][65];   // padded: bank-conflict-free row access
    __shared__ float kss[64];

    const int bh  = blockIdx.x;     // 0..63
    const int lch = blockIdx.y;     // 0..7
    const int b = bh >> 3;
    const int h = bh & 7;
    const int tid = threadIdx.x;

    for (int i = tid; i < 4096; i += 256)
        kvs[i >> 6][i & 63] = g_KV[(size_t)bh * 4096 + i];
    if (tid < 64) kss[tid] = g_KS[bh * 64 + tid];
    __syncthreads();

    const int wid  = tid >> 5;
    const int lane = tid & 31;
    const float ks0 = kss[lane];
    const float ks1 = kss[lane + 32];

    for (int r = lch * 1024 + wid; r < (lch + 1) * 1024; r += 8) {
        size_t qoff = ((size_t)b * L_ + r) * D3_ + h * DH_;
        float q0 = g_QKV[qoff + lane];
        float q1 = g_QKV[qoff + lane + 32];

        float p = q0 * ks0 + q1 * ks1;
        #pragma unroll
        for (int o = 16; o > 0; o >>= 1) p += __shfl_xor_sync(0xffffffffu, p, o);
        float z = 1.0f / (p + EPS_);

        float a0 = 0.f, a1 = 0.f;
        #pragma unroll
        for (int d = 0; d < 32; d++) {
            float qd = __shfl_sync(0xffffffffu, q0, d);
            a0 = fmaf(qd, kvs[lane][d], a0);
            a1 = fmaf(qd, kvs[lane + 32][d], a1);
        }
        #pragma unroll
        for (int d = 0; d < 32; d++) {
            float qd = __shfl_sync(0xffffffffu, q1, d);
            a0 = fmaf(qd, kvs[lane][d + 32], a0);
            a1 = fmaf(qd, kvs[lane + 32][d + 32], a1);
        }

        size_t ooff = ((size_t)b * L_ + r) * D_ + h * DH_;
        g_ATT[ooff + lane]      = a0 * z;
        g_ATT[ooff + lane + 32] = a1 * z;
    }
}

// ---------------------------------------------------------------------------
// Launch
// ---------------------------------------------------------------------------
extern "C" void kernel_launch(void* const* d_in, const int* in_sizes, int n_in,
                              void* d_out, int out_size) {
    const float* q     = (const float*)d_in[0];
    const float* k     = (const float*)d_in[1];
    const float* v     = (const float*)d_in[2];
    const float* w_qkv = (const float*)d_in[3];
    const float* w_out = (const float*)d_in[4];
    const float* b_out = (const float*)d_in[5];
    float* out = (float*)d_out;

    float *X, *QKV, *ATT;
    cudaGetSymbolAddress((void**)&X,   g_X);
    cudaGetSymbolAddress((void**)&QKV, g_QKV);
    cudaGetSymbolAddress((void**)&ATT, g_ATT);

    // 1) concat -> X
    concat_k<<<32768, 256>>>((const float4*)q, (const float4*)k, (const float4*)v);
    // 2) QKV = X @ W_qkv^T     (M=65536, N=1536, K=1536)
    sgemm_nt<<<dim3(12, 512), 256>>>(X, w_qkv, nullptr, QKV, 1536, 1536);
    // 3) elu+1 on q,k parts
    elu_k<<<65536, 256>>>();
    // 4) kv-state partials, 5) reduce
    kv_kernel<<<dim3(64, NSC), 256>>>();
    kv_reduce<<<1040, 256>>>();
    // 6) apply attention
    attn_k<<<dim3(64, 8), 256>>>();
    // 7) out = ATT @ W_out^T + b_out   (M=65536, N=512, K=512)
    sgemm_nt<<<dim3(4, 512), 256>>>(ATT, w_out, b_out, out, 512, 512);
}